// round 2
// baseline (speedup 1.0000x reference)
#include <cuda_runtime.h>

#define NN     4096
#define NFEAT  1024
#define HALL   64      // 8 heads * 8 hid
#define NHEADS 8
#define NHID   8
#define NC     16
#define MAXDEG 512
#define SPLITS 4
#define KC     (NFEAT / SPLITS)   // 256
#define BM     128
#define BN     64
#define BK     16
#define ALPHA  0.2f

// ---- scratch (device globals: no allocation allowed) ----
__device__ int   d_nbr[NN * MAXDEG];          // 8 MB neighbor lists
__device__ int   d_deg[NN];
__device__ float d_Wc [NFEAT * HALL];         // repacked head weights [K,64]
__device__ float d_Whp[SPLITS * NN * HALL];   // split-K partials
__device__ float d_Wh [NN * HALL];            // x @ W_all
__device__ float d_fsrc[NHEADS * NN];
__device__ float d_fdst[NHEADS * NN];
__device__ float d_h  [NN * HALL];            // layer-1 output (post-ELU)
__device__ float d_Wh2[NN * NC];
__device__ float d_f2s[NN];
__device__ float d_f2d[NN];

// ---- 1. build neighbor lists from dense adj (single 64MB pass) ----
__global__ __launch_bounds__(256) void build_nbr(const float4* __restrict__ adj)
{
    int i = blockIdx.x;
    __shared__ int cnt;
    if (threadIdx.x == 0) cnt = 0;
    __syncthreads();
    const float4* row = adj + (size_t)i * (NN / 4);
    int* nb = d_nbr + (size_t)i * MAXDEG;
    for (int q = threadIdx.x; q < NN / 4; q += 256) {
        float4 v = row[q];
        int j = q * 4;
        if (v.x > 0.0f) { int p = atomicAdd(&cnt, 1); if (p < MAXDEG) nb[p] = j;     }
        if (v.y > 0.0f) { int p = atomicAdd(&cnt, 1); if (p < MAXDEG) nb[p] = j + 1; }
        if (v.z > 0.0f) { int p = atomicAdd(&cnt, 1); if (p < MAXDEG) nb[p] = j + 2; }
        if (v.w > 0.0f) { int p = atomicAdd(&cnt, 1); if (p < MAXDEG) nb[p] = j + 3; }
    }
    __syncthreads();
    if (threadIdx.x == 0) d_deg[i] = cnt < MAXDEG ? cnt : MAXDEG;
}

// ---- 2. repack W_heads [8,1024,8] -> Wc [1024,64] ----
__global__ void repack_W(const float* __restrict__ W_heads)
{
    int idx = blockIdx.x * blockDim.x + threadIdx.x;   // over 1024*64
    if (idx < NFEAT * HALL) {
        int k = idx >> 6, n = idx & 63;
        d_Wc[idx] = W_heads[(n >> 3) * (NFEAT * NHID) + k * NHID + (n & 7)];
    }
}

// ---- 3. SGEMM: Wh_partial[split] = x[:,k0:k0+256] @ Wc[k0:k0+256,:] ----
__global__ __launch_bounds__(256) void gemm_wh(const float* __restrict__ x)
{
    __shared__ float As[BK][BM];   // transposed: As[k][m]
    __shared__ float Bs[BK][BN];
    int bm    = blockIdx.x * BM;
    int split = blockIdx.y;
    int k0    = split * KC;
    int tid = threadIdx.x;
    int tx = tid & 15;           // column group (4 cols)
    int ty = tid >> 4;           // row group (8 rows)
    int m0 = ty * 8, n0 = tx * 4;

    float acc[8][4];
#pragma unroll
    for (int r = 0; r < 8; r++)
#pragma unroll
        for (int c = 0; c < 4; c++) acc[r][c] = 0.0f;

    for (int kc = 0; kc < KC; kc += BK) {
        // A tile: 128x16 floats = 512 float4, 2 per thread; transpose on store
#pragma unroll
        for (int r = 0; r < 2; r++) {
            int idx = tid + r * 256;
            int m = idx >> 2, q = idx & 3;
            float4 v = *(const float4*)(x + (size_t)(bm + m) * NFEAT + k0 + kc + q * 4);
            As[q * 4 + 0][m] = v.x;
            As[q * 4 + 1][m] = v.y;
            As[q * 4 + 2][m] = v.z;
            As[q * 4 + 3][m] = v.w;
        }
        // B tile: 16x64 floats = 256 float4, 1 per thread
        {
            int kk = tid >> 4, n4 = tid & 15;
            *(float4*)&Bs[kk][n4 * 4] =
                *(const float4*)(d_Wc + (size_t)(k0 + kc + kk) * HALL + n4 * 4);
        }
        __syncthreads();
#pragma unroll
        for (int kk = 0; kk < BK; kk++) {
            float4 a0 = *(float4*)&As[kk][m0];
            float4 a1 = *(float4*)&As[kk][m0 + 4];
            float4 b  = *(float4*)&Bs[kk][n0];
            float av[8] = {a0.x, a0.y, a0.z, a0.w, a1.x, a1.y, a1.z, a1.w};
            float bv[4] = {b.x, b.y, b.z, b.w};
#pragma unroll
            for (int r = 0; r < 8; r++)
#pragma unroll
                for (int c = 0; c < 4; c++)
                    acc[r][c] += av[r] * bv[c];
        }
        __syncthreads();
    }
    float* outp = d_Whp + (size_t)split * NN * HALL;
#pragma unroll
    for (int r = 0; r < 8; r++)
        *(float4*)(outp + (size_t)(bm + m0 + r) * HALL + n0) =
            make_float4(acc[r][0], acc[r][1], acc[r][2], acc[r][3]);
}

// ---- 4. reduce split-K partials ----
__global__ void reduce_wh()
{
    int idx = blockIdx.x * blockDim.x + threadIdx.x;   // NN*HALL
    d_Wh[idx] = d_Whp[idx] + d_Whp[NN * HALL + idx]
              + d_Whp[2 * NN * HALL + idx] + d_Whp[3 * NN * HALL + idx];
}

// ---- 5. attention logits per node: f_src/f_dst for 8 heads ----
__global__ void calc_f(const float* __restrict__ a_heads)
{
    int idx = blockIdx.x * blockDim.x + threadIdx.x;   // NN*NHEADS
    int i = idx >> 3, h = idx & 7;
    const float* w = d_Wh + (size_t)i * HALL + h * NHID;
    const float* a = a_heads + h * (2 * NHID);
    float s = 0.0f, d = 0.0f;
#pragma unroll
    for (int k = 0; k < NHID; k++) {
        float v = w[k];
        s += v * a[k];
        d += v * a[NHID + k];
    }
    d_fsrc[h * NN + i] = s;
    d_fdst[h * NN + i] = d;
}

// ---- 6. layer-1 sparse attention + ELU (one 64-thread block per row) ----
__global__ __launch_bounds__(64) void attn1()
{
    int i = blockIdx.x;
    int t = threadIdx.x;        // t = h*8 + c
    int h = t >> 3;
    int deg = d_deg[i];
    float fs = d_fsrc[h * NN + i];
    const int* __restrict__ nb = d_nbr + (size_t)i * MAXDEG;
    float s = 0.0f, acc = 0.0f;
    for (int q = 0; q < deg; q++) {
        int j = nb[q];
        float e = fs + d_fdst[h * NN + j];
        e = e > 0.0f ? e : ALPHA * e;
        float p = __expf(e);             // shift-free softmax (|e| small)
        s += p;
        acc += p * d_Wh[(size_t)j * HALL + t];
    }
    float v = acc / s;
    d_h[(size_t)i * HALL + t] = v > 0.0f ? v : expm1f(v);   // ELU
}

// ---- 7. layer-2 projection: Wh2 = h @ W_final[64,16] ----
__global__ void gemm_wh2(const float* __restrict__ Wf)
{
    int idx = blockIdx.x * blockDim.x + threadIdx.x;   // NN*NC
    int i = idx >> 4, c = idx & 15;
    const float* hr = d_h + (size_t)i * HALL;
    float s = 0.0f;
#pragma unroll
    for (int k = 0; k < HALL; k++) s += hr[k] * Wf[k * NC + c];
    d_Wh2[idx] = s;
}

// ---- 8. layer-2 logits ----
__global__ void calc_f2(const float* __restrict__ a_final)
{
    int i = blockIdx.x * blockDim.x + threadIdx.x;
    if (i >= NN) return;
    float s = 0.0f, d = 0.0f;
#pragma unroll
    for (int c = 0; c < NC; c++) {
        float w = d_Wh2[i * NC + c];
        s += w * a_final[c];
        d += w * a_final[NC + c];
    }
    d_f2s[i] = s;
    d_f2d[i] = d;
}

// ---- 9. layer-2 sparse attention + log_softmax (one warp per row) ----
__global__ __launch_bounds__(128) void attn2(float* __restrict__ out)
{
    int i = blockIdx.x * 4 + (threadIdx.x >> 5);
    int lane = threadIdx.x & 31;
    int c = lane & 15, half = lane >> 4;
    int deg = d_deg[i];
    float fs = d_f2s[i];
    const int* __restrict__ nb = d_nbr + (size_t)i * MAXDEG;
    float s = 0.0f, acc = 0.0f;
    for (int q = half; q < deg; q += 2) {
        int j = nb[q];
        float e = fs + d_f2d[j];
        e = e > 0.0f ? e : ALPHA * e;
        float p = __expf(e);
        s += p;
        acc += p * d_Wh2[(size_t)j * NC + c];
    }
    acc += __shfl_xor_sync(0xffffffffu, acc, 16);
    s   += __shfl_xor_sync(0xffffffffu, s, 16);
    float o = acc / s;
    // log_softmax over 16 classes (lanes c and c+16 hold identical values)
    float m = o;
#pragma unroll
    for (int d = 8; d; d >>= 1) m = fmaxf(m, __shfl_xor_sync(0xffffffffu, m, d));
    float ex = __expf(o - m);
    float se = ex;
#pragma unroll
    for (int d = 8; d; d >>= 1) se += __shfl_xor_sync(0xffffffffu, se, d);
    if (half == 0) out[(size_t)i * NC + c] = o - m - logf(se);
}

extern "C" void kernel_launch(void* const* d_in, const int* in_sizes, int n_in,
                              void* d_out, int out_size)
{
    const float* x       = (const float*)d_in[0];
    const float* adj     = (const float*)d_in[1];
    const float* W_heads = (const float*)d_in[2];
    const float* a_heads = (const float*)d_in[3];
    const float* W_final = (const float*)d_in[4];
    const float* a_final = (const float*)d_in[5];
    float* out = (float*)d_out;

    build_nbr<<<NN, 256>>>((const float4*)adj);
    repack_W<<<(NFEAT * HALL + 255) / 256, 256>>>(W_heads);
    gemm_wh<<<dim3(NN / BM, SPLITS), 256>>>(x);
    reduce_wh<<<NN * HALL / 256, 256>>>();
    calc_f<<<NN * NHEADS / 256, 256>>>(a_heads);
    attn1<<<NN, 64>>>();
    gemm_wh2<<<NN * NC / 256, 256>>>(W_final);
    calc_f2<<<(NN + 255) / 256, 256>>>(a_final);
    attn2<<<NN / 4, 128>>>(out);
}